// round 6
// baseline (speedup 1.0000x reference)
#include <cuda_runtime.h>

#define THREADS 256
#define BLOCKS_PER_SEG 32

__global__ void zero_out_kernel(float* out, int n) {
    int i = blockIdx.x * blockDim.x + threadIdx.x;
    if (i < n) out[i] = 0.0f;
}

__global__ __launch_bounds__(THREADS) void trajectory_score_kernel(
    const float4* __restrict__ up, const float4* __restrict__ uo,
    const float* __restrict__ hArr, const float* __restrict__ lamArr,
    const float* __restrict__ thArr, float* __restrict__ out,
    int B, int groupsPerSeg, int vec4PerSeg)
{
    int seg  = blockIdx.x / BLOCKS_PER_SEG;
    int part = blockIdx.x - seg * BLOCKS_PER_SEG;

    float h   = hArr[seg];
    float lam = lamArr[seg];
    float th  = thArr[seg];
    float inv_th = 1.0f / th;
    float c = h * lam / (1.0f - expf(-lam));   // h * lam / (1 - e^-lam)
    float q = 1.0f - h;

    const float4* upS = up + (size_t)seg * vec4PerSeg;
    const float4* uoS = uo + (size_t)seg * vec4PerSeg;

    float acc_log = 0.0f;
    float acc_hit = 0.0f;

    for (int g = part * THREADS + threadIdx.x; g < groupsPerSeg;
         g += BLOCKS_PER_SEG * THREADS) {
        float4 a0 = __ldg(&upS[3 * g + 0]);
        float4 a1 = __ldg(&upS[3 * g + 1]);
        float4 a2 = __ldg(&upS[3 * g + 2]);
        float4 b0 = __ldg(&uoS[3 * g + 0]);
        float4 b1 = __ldg(&uoS[3 * g + 1]);
        float4 b2 = __ldg(&uoS[3 * g + 2]);

        float d0  = a0.x - b0.x, d1  = a0.y - b0.y, d2  = a0.z - b0.z;
        float d3  = a0.w - b0.w, d4  = a1.x - b1.x, d5  = a1.y - b1.y;
        float d6  = a1.z - b1.z, d7  = a1.w - b1.w, d8  = a2.x - b2.x;
        float d9  = a2.y - b2.y, d10 = a2.z - b2.z, d11 = a2.w - b2.w;

        float s2[4];
        s2[0] = d0 * d0 + d1 * d1 + d2 * d2;
        s2[1] = d3 * d3 + d4 * d4 + d5 * d5;
        s2[2] = d6 * d6 + d7 * d7 + d8 * d8;
        s2[3] = d9 * d9 + d10 * d10 + d11 * d11;

        #pragma unroll
        for (int r = 0; r < 4; r++) {
            float s = s2[r];
            bool close = s < th;
            float ph = c * expf(-lam * (s * inv_th));
            float p  = ph + q;
            float ratio = ph / p;
            if (close)                   acc_log += logf(p);
            if (close && ratio > 0.95f)  acc_hit += ratio;
        }
    }

    // warp reduce
    #pragma unroll
    for (int o = 16; o > 0; o >>= 1) {
        acc_log += __shfl_down_sync(0xffffffffu, acc_log, o);
        acc_hit += __shfl_down_sync(0xffffffffu, acc_hit, o);
    }

    __shared__ float s_log[THREADS / 32];
    __shared__ float s_hit[THREADS / 32];
    int lane = threadIdx.x & 31;
    int warp = threadIdx.x >> 5;
    if (lane == 0) { s_log[warp] = acc_log; s_hit[warp] = acc_hit; }
    __syncthreads();

    if (threadIdx.x == 0) {
        float tl = 0.0f, thit = 0.0f;
        #pragma unroll
        for (int w = 0; w < THREADS / 32; w++) { tl += s_log[w]; thit += s_hit[w]; }
        atomicAdd(&out[seg],         tl);
        atomicAdd(&out[B + seg],     thit);
        atomicAdd(&out[2 * B + seg], thit);
    }
}

extern "C" void kernel_launch(void* const* d_in, const int* in_sizes, int n_in,
                              void* d_out, int out_size) {
    const float* up  = (const float*)d_in[0];  // u_pred [N,3]
    const float* uo  = (const float*)d_in[1];  // u_obs  [N,3]
    const float* h   = (const float*)d_in[2];  // [B]
    const float* lam = (const float*)d_in[3];  // [B]
    const float* th  = (const float*)d_in[4];  // [B]
    float* out = (float*)d_out;                // [3*B]

    int B    = in_sizes[2];
    int N    = in_sizes[0] / 3;
    int nper = N / B;                 // 100000, divisible by 4
    int groupsPerSeg = nper / 4;      // 25000
    int vec4PerSeg   = (nper * 3) / 4; // 75000

    zero_out_kernel<<<1, 256>>>(out, out_size);
    trajectory_score_kernel<<<B * BLOCKS_PER_SEG, THREADS>>>(
        (const float4*)up, (const float4*)uo, h, lam, th, out,
        B, groupsPerSeg, vec4PerSeg);
}

// round 9
// speedup vs baseline: 1.0092x; 1.0092x over previous
#include <cuda_runtime.h>

#define THREADS 256
#define BLOCKS_PER_SEG 32

__global__ void zero_out_kernel(float* out, int n) {
    int i = blockIdx.x * blockDim.x + threadIdx.x;
    if (i < n) out[i] = 0.0f;
}

__global__ __launch_bounds__(THREADS) void trajectory_score_kernel(
    const float4* __restrict__ up, const float4* __restrict__ uo,
    const float* __restrict__ hArr, const float* __restrict__ lamArr,
    const float* __restrict__ thArr, float* __restrict__ out,
    int B, int groupsPerSeg, int vec4PerSeg)
{
    int seg  = blockIdx.x / BLOCKS_PER_SEG;
    int part = blockIdx.x - seg * BLOCKS_PER_SEG;

    float h   = hArr[seg];
    float lam = lamArr[seg];
    float th  = thArr[seg];
    // c = h * lam / (1 - e^-lam); full-precision here (once per block)
    float c = h * lam / (1.0f - expf(-lam));
    float q = 1.0f - h;
    // exponent as exp2: e^{-lam * s / th} = 2^{s * nk2}
    float nk2 = -(lam / th) * 1.44269504088896340736f;

    const float4* upS = up + (size_t)seg * vec4PerSeg;
    const float4* uoS = uo + (size_t)seg * vec4PerSeg;

    float acc_log = 0.0f;
    float acc_hit = 0.0f;

    for (int g = part * THREADS + threadIdx.x; g < groupsPerSeg;
         g += BLOCKS_PER_SEG * THREADS) {
        float4 a0 = __ldg(&upS[3 * g + 0]);
        float4 a1 = __ldg(&upS[3 * g + 1]);
        float4 a2 = __ldg(&upS[3 * g + 2]);
        float4 b0 = __ldg(&uoS[3 * g + 0]);
        float4 b1 = __ldg(&uoS[3 * g + 1]);
        float4 b2 = __ldg(&uoS[3 * g + 2]);

        float d0  = a0.x - b0.x, d1  = a0.y - b0.y, d2  = a0.z - b0.z;
        float d3  = a0.w - b0.w, d4  = a1.x - b1.x, d5  = a1.y - b1.y;
        float d6  = a1.z - b1.z, d7  = a1.w - b1.w, d8  = a2.x - b2.x;
        float d9  = a2.y - b2.y, d10 = a2.z - b2.z, d11 = a2.w - b2.w;

        float s2[4];
        s2[0] = d0 * d0 + d1 * d1 + d2 * d2;
        s2[1] = d3 * d3 + d4 * d4 + d5 * d5;
        s2[2] = d6 * d6 + d7 * d7 + d8 * d8;
        s2[3] = d9 * d9 + d10 * d10 + d11 * d11;

        #pragma unroll
        for (int r = 0; r < 4; r++) {
            float s = s2[r];
            bool close = s < th;
            // ph = c * 2^(nk2 * s)  : 1 FMUL + 1 MUFU.EX2 + 1 FMUL
            float ph = c * exp2f(s * nk2);
            float p  = ph + q;
            float rp = __frcp_rn(p);         // MUFU.RCP (+NR)
            float ratio = ph * rp;
            float lp = __logf(p);            // MUFU.LG2 + FMUL
            acc_log += close ? lp : 0.0f;
            acc_hit += (close && ratio > 0.95f) ? ratio : 0.0f;
        }
    }

    // warp reduce
    #pragma unroll
    for (int o = 16; o > 0; o >>= 1) {
        acc_log += __shfl_down_sync(0xffffffffu, acc_log, o);
        acc_hit += __shfl_down_sync(0xffffffffu, acc_hit, o);
    }

    __shared__ float s_log[THREADS / 32];
    __shared__ float s_hit[THREADS / 32];
    int lane = threadIdx.x & 31;
    int warp = threadIdx.x >> 5;
    if (lane == 0) { s_log[warp] = acc_log; s_hit[warp] = acc_hit; }
    __syncthreads();

    if (threadIdx.x == 0) {
        float tl = 0.0f, thit = 0.0f;
        #pragma unroll
        for (int w = 0; w < THREADS / 32; w++) { tl += s_log[w]; thit += s_hit[w]; }
        atomicAdd(&out[seg],         tl);
        atomicAdd(&out[B + seg],     thit);
        atomicAdd(&out[2 * B + seg], thit);
    }
}

extern "C" void kernel_launch(void* const* d_in, const int* in_sizes, int n_in,
                              void* d_out, int out_size) {
    const float* up  = (const float*)d_in[0];  // u_pred [N,3]
    const float* uo  = (const float*)d_in[1];  // u_obs  [N,3]
    const float* h   = (const float*)d_in[2];  // [B]
    const float* lam = (const float*)d_in[3];  // [B]
    const float* th  = (const float*)d_in[4];  // [B]
    float* out = (float*)d_out;                // [3*B]

    int B    = in_sizes[2];
    int N    = in_sizes[0] / 3;
    int nper = N / B;                  // 100000, divisible by 4
    int groupsPerSeg = nper / 4;       // 25000
    int vec4PerSeg   = (nper * 3) / 4; // 75000

    zero_out_kernel<<<1, 256>>>(out, out_size);
    trajectory_score_kernel<<<B * BLOCKS_PER_SEG, THREADS>>>(
        (const float4*)up, (const float4*)uo, h, lam, th, out,
        B, groupsPerSeg, vec4PerSeg);
}